// round 14
// baseline (speedup 1.0000x reference)
#include <cuda_runtime.h>
#include <cuda_bf16.h>
#include <cstdint>

#define NN 50000
#define NE 800000
#define INC 256
#define HC  128

#define NROWS_PAD 50048   // 391 * 128

// Scratch (no cudaMalloc allowed)
__device__ float g_h[(size_t)NN * HC];
__device__ float g_dis[NN];
__device__ int   g_cnt[NN];
__device__ int   g_off[NN + 1];
__device__ int   g_cursor[NN];
__device__ int2  g_csr[NE];                   // {row | col<<16, ew_bits}
__device__ __nv_bfloat16 g_wcat[512 * 128];   // [Whi(256); Wlo(256)]

// Build-kernel grid config: 148 blocks (1/SM, co-resident) x 256 threads
#define BB 148
#define BT 256
#define SEG ((NN + BB - 1) / BB)     // 338 nodes per block segment
__device__ int g_bsum[BB];
__device__ int g_boff[BB];
__device__ unsigned g_barcnt;
__device__ volatile unsigned g_barsense;

// ---------------------------------------------------------------------------
// Prep: zero g_cnt, reset barrier, build wcat = [Whi(256); Wlo(256)] bf16
// ---------------------------------------------------------------------------
__global__ void k_prep(const float* __restrict__ W) {
    int i = blockIdx.x * blockDim.x + threadIdx.x;   // 65536 threads
    if (i == 0) { g_barcnt = 0; g_barsense = 0; }
    if (i < NN) g_cnt[i] = 0;
    if (i < 512 * 128) {
        int kr = i >> 7, c = i & 127;
        float w = W[(size_t)(kr & 255) * 128 + c];
        __nv_bfloat16 h = __float2bfloat16(w);
        g_wcat[i] = (kr >= 256) ? __float2bfloat16(w - __bfloat162float(h)) : h;
    }
}

// ---------------------------------------------------------------------------
// Fused CSR build: count -> scan -> fill -> degdis, one persistent launch
// ---------------------------------------------------------------------------
__device__ __forceinline__ void grid_barrier(unsigned& sense) {
    __syncthreads();
    if (threadIdx.x == 0) {
        sense ^= 1u;
        __threadfence();
        unsigned arr = atomicAdd(&g_barcnt, 1);
        if (arr == BB - 1) {
            g_barcnt = 0;
            __threadfence();
            g_barsense = sense;
        } else {
            while (g_barsense != sense) __nanosleep(64);
        }
        __threadfence();
    }
    __syncthreads();
}

__global__ __launch_bounds__(BT, 1)
void k_build(const int* __restrict__ ei, const float* __restrict__ ew) {
    __shared__ int warpsum[8];
    __shared__ int s_boff;
    int tid = threadIdx.x, lane = tid & 31, wid = tid >> 5;
    int gtid = blockIdx.x * BT + tid;
    unsigned sense = 0;

    // --- Phase A: histogram of destination counts ---
    for (int e = gtid; e < NE; e += BB * BT)
        atomicAdd(&g_cnt[ei[NE + e]], 1);
    grid_barrier(sense);

    // --- Phase B: per-block segment sum ---
    {
        int start = blockIdx.x * SEG;
        int end = min(NN, start + SEG);
        int sum = 0;
        for (int i = start + tid; i < end; i += BT) sum += g_cnt[i];
#pragma unroll
        for (int o = 16; o > 0; o >>= 1)
            sum += __shfl_xor_sync(0xFFFFFFFFu, sum, o);
        if (lane == 0) warpsum[wid] = sum;
        __syncthreads();
        if (tid == 0) {
            int t = 0;
#pragma unroll
            for (int w = 0; w < 8; w++) t += warpsum[w];
            g_bsum[blockIdx.x] = t;
        }
    }
    grid_barrier(sense);

    // --- Phase C: block 0 scans the 148 block sums ---
    if (blockIdx.x == 0) {
        int v = (tid < BB) ? g_bsum[tid] : 0;
        int x = v;
#pragma unroll
        for (int o = 1; o < 32; o <<= 1) {
            int t = __shfl_up_sync(0xFFFFFFFFu, x, o);
            if (lane >= o) x += t;
        }
        if (lane == 31) warpsum[wid] = x;
        __syncthreads();
        if (wid == 0) {
            int w = (lane < 8) ? warpsum[lane] : 0;
#pragma unroll
            for (int o = 1; o < 8; o <<= 1) {
                int t = __shfl_up_sync(0xFFFFFFFFu, w, o);
                if (lane >= o) w += t;
            }
            if (lane < 8) warpsum[lane] = w;
        }
        __syncthreads();
        int pre = (wid > 0) ? warpsum[wid - 1] : 0;
        int incl = pre + x;
        if (tid < BB) g_boff[tid] = incl - v;
        if (tid == BB - 1) g_off[NN] = incl;
    }
    grid_barrier(sense);

    // --- Phase D: per-block exclusive scan of segment ---
    {
        if (tid == 0) s_boff = g_boff[blockIdx.x];
        __syncthreads();
        int base_off = s_boff;
        int start = blockIdx.x * SEG;
        int end = min(NN, start + SEG);
        int carry = 0;
        for (int base = start; base < end; base += BT) {
            int i = base + tid;
            int v = (i < end) ? g_cnt[i] : 0;
            int x = v;
#pragma unroll
            for (int o = 1; o < 32; o <<= 1) {
                int t = __shfl_up_sync(0xFFFFFFFFu, x, o);
                if (lane >= o) x += t;
            }
            __syncthreads();
            if (lane == 31) warpsum[wid] = x;
            __syncthreads();
            int wpre = 0;
#pragma unroll
            for (int w = 0; w < 8; w++) {
                int ws = warpsum[w];
                if (w < wid) wpre += ws;
            }
            int tot = 0;
#pragma unroll
            for (int w = 0; w < 8; w++) tot += warpsum[w];
            int excl = carry + wpre + x - v;
            if (i < end) {
                int o = base_off + excl;
                g_off[i] = o;
                g_cursor[i] = o;
            }
            carry += tot;
        }
    }
    grid_barrier(sense);

    // --- Phase E: fill CSR buckets ---
    for (int e = gtid; e < NE; e += BB * BT) {
        int r = ei[e];
        int c = ei[NE + e];
        int pos = atomicAdd(&g_cursor[c], 1);
        g_csr[pos] = make_int2(r | (c << 16), __float_as_int(ew[e]));
    }
    grid_barrier(sense);

    // --- Phase F: degree + dis (warp per node) ---
    {
        int warpg = (blockIdx.x * BT + tid) >> 5;   // 1184 warps
        for (int node = warpg; node < NN; node += BB * (BT / 32)) {
            int s = g_off[node], e = g_off[node + 1];
            float sum = 0.0f;
            for (int j = s + lane; j < e; j += 32)
                sum += __int_as_float(g_csr[j].y);
#pragma unroll
            for (int o = 16; o > 0; o >>= 1)
                sum += __shfl_xor_sync(0xFFFFFFFFu, sum, o);
            if (lane == 0) g_dis[node] = rsqrtf(1.0f + sum);
        }
    }
}

// ---------------------------------------------------------------------------
// Tensor GEMM, chunked 3-product split (x read once per chunk):
// Ahi*Whi + Ahi*Wlo + Alo*Whi accumulated in fp32.
// ---------------------------------------------------------------------------
#define GM 128
#define GK 32
#define NCH (INC / GK)      // 8 chunks
#define ASTR 40             // bf16 units (80B row stride: ldmatrix conflict-free)
#define BSTR 136            // (272B row stride)

#define AHI_OFF 0                          // [2][GM*ASTR] bf16
#define ALO_OFF (2 * GM * ASTR)            // [2][GM*ASTR]
#define B_OFF   (4 * GM * ASTR)            // [2][64*BSTR]
#define SMEM_ELEMS (4 * GM * ASTR + 2 * 64 * BSTR)
#define SMEM_BYTES (SMEM_ELEMS * 2)

__device__ __forceinline__ void cp16(void* s, const void* g) {
    uint32_t sa = (uint32_t)__cvta_generic_to_shared(s);
    asm volatile("cp.async.cg.shared.global [%0], [%1], 16;\n" :: "r"(sa), "l"(g));
}
__device__ __forceinline__ void ldm_x4(uint32_t* r, uint32_t a) {
    asm volatile("ldmatrix.sync.aligned.m8n8.x4.shared.b16 {%0,%1,%2,%3}, [%4];"
                 : "=r"(r[0]), "=r"(r[1]), "=r"(r[2]), "=r"(r[3]) : "r"(a));
}
__device__ __forceinline__ void ldm_x4t(uint32_t* r, uint32_t a) {
    asm volatile("ldmatrix.sync.aligned.m8n8.x4.trans.shared.b16 {%0,%1,%2,%3}, [%4];"
                 : "=r"(r[0]), "=r"(r[1]), "=r"(r[2]), "=r"(r[3]) : "r"(a));
}
__device__ __forceinline__ void mma16816(float* c, const uint32_t* a, const uint32_t* b) {
    asm volatile("mma.sync.aligned.m16n8k16.row.col.f32.bf16.bf16.f32 "
                 "{%0,%1,%2,%3}, {%4,%5,%6,%7}, {%8,%9}, {%0,%1,%2,%3};"
                 : "+f"(c[0]), "+f"(c[1]), "+f"(c[2]), "+f"(c[3])
                 : "r"(a[0]), "r"(a[1]), "r"(a[2]), "r"(a[3]), "r"(b[0]), "r"(b[1]));
}

__device__ __forceinline__ uint2 pack_hi(float4 v) {
    __nv_bfloat16 h0 = __float2bfloat16(v.x), h1 = __float2bfloat16(v.y);
    __nv_bfloat16 h2 = __float2bfloat16(v.z), h3 = __float2bfloat16(v.w);
    uint2 p;
    p.x = ((uint32_t)__bfloat16_as_ushort(h1) << 16) | __bfloat16_as_ushort(h0);
    p.y = ((uint32_t)__bfloat16_as_ushort(h3) << 16) | __bfloat16_as_ushort(h2);
    return p;
}
__device__ __forceinline__ uint2 pack_lo(float4 v) {
    __nv_bfloat16 h0 = __float2bfloat16(v.x), h1 = __float2bfloat16(v.y);
    __nv_bfloat16 h2 = __float2bfloat16(v.z), h3 = __float2bfloat16(v.w);
    __nv_bfloat16 l0 = __float2bfloat16(v.x - __bfloat162float(h0));
    __nv_bfloat16 l1 = __float2bfloat16(v.y - __bfloat162float(h1));
    __nv_bfloat16 l2 = __float2bfloat16(v.z - __bfloat162float(h2));
    __nv_bfloat16 l3 = __float2bfloat16(v.w - __bfloat162float(h3));
    uint2 p;
    p.x = ((uint32_t)__bfloat16_as_ushort(l1) << 16) | __bfloat16_as_ushort(l0);
    p.y = ((uint32_t)__bfloat16_as_ushort(l3) << 16) | __bfloat16_as_ushort(l2);
    return p;
}

__global__ __launch_bounds__(256, 2)
void k_gemm_mma(const float* __restrict__ x) {
    extern __shared__ __nv_bfloat16 smem[];
    __nv_bfloat16* Ahi = smem + AHI_OFF;
    __nv_bfloat16* Alo = smem + ALO_OFF;
    __nv_bfloat16* Bs  = smem + B_OFF;

    int tid = threadIdx.x;
    int wid = tid >> 5, lane = tid & 31;
    int wm = wid >> 1, wn = wid & 1;       // 4x2 warps: 32 rows x 64 cols
    int rowBase = blockIdx.x * GM;

    float acc[2][8][4];
#pragma unroll
    for (int i = 0; i < 2; i++)
#pragma unroll
        for (int j = 0; j < 8; j++)
#pragma unroll
            for (int q = 0; q < 4; q++) acc[i][j][q] = 0.0f;

    float4 xstage[4];

    auto ldx = [&](int c) {
        int xcol = c * GK;
#pragma unroll
        for (int l = 0; l < 4; l++) {
            int idx = tid + l * 256;
            int r  = idx >> 3;
            int c8 = idx & 7;
            int gr = rowBase + r;
            float4 v = make_float4(0.f, 0.f, 0.f, 0.f);
            if (gr < NN)
                v = *reinterpret_cast<const float4*>(&x[(size_t)gr * INC + xcol + c8 * 4]);
            xstage[l] = v;
        }
    };
    auto stx = [&](int buf) {
#pragma unroll
        for (int l = 0; l < 4; l++) {
            int idx = tid + l * 256;
            int r  = idx >> 3;
            int c8 = idx & 7;
            *reinterpret_cast<uint2*>(&Ahi[buf * GM * ASTR + r * ASTR + c8 * 4]) =
                pack_hi(xstage[l]);
            *reinterpret_cast<uint2*>(&Alo[buf * GM * ASTR + r * ASTR + c8 * 4]) =
                pack_lo(xstage[l]);
        }
    };
    auto ldb = [&](int c, int buf) {
        int kk = c * GK;
#pragma unroll
        for (int l = 0; l < 4; l++) {
            int idx = tid + l * 256;
            int kr = idx >> 4;            // 64 rows (0..31 hi, 32..63 lo)
            int cq = idx & 15;
            int srow = (kr < 32) ? (kk + kr) : (256 + kk + (kr - 32));
            cp16(&Bs[buf * 64 * BSTR + kr * BSTR + cq * 8],
                 &g_wcat[(size_t)srow * 128 + cq * 8]);
        }
        asm volatile("cp.async.commit_group;\n");
    };

    ldx(0); ldb(0, 0); stx(0);
    asm volatile("cp.async.wait_group 0;\n");
    __syncthreads();

    for (int c = 0; c < NCH; c++) {
        int cur = c & 1, nxt = cur ^ 1;
        bool more = (c + 1 < NCH);
        if (more) { ldx(c + 1); ldb(c + 1, nxt); }

        uint32_t ahib = (uint32_t)__cvta_generic_to_shared(&Ahi[cur * GM * ASTR]);
        uint32_t alob = (uint32_t)__cvta_generic_to_shared(&Alo[cur * GM * ASTR]);
        uint32_t bb   = (uint32_t)__cvta_generic_to_shared(&Bs[cur * 64 * BSTR]);
        int lr = lane & 15, lc = (lane >> 4) * 8;

#pragma unroll
        for (int ks = 0; ks < 2; ks++) {
            int kb = ks * 16;
            uint32_t af[2][4], bf[4][4];

            // pass 1: Ahi x Whi
#pragma unroll
            for (int mt = 0; mt < 2; mt++)
                ldm_x4(af[mt], ahib + ((wm * 32 + mt * 16 + lr) * ASTR + kb + lc) * 2);
#pragma unroll
            for (int nt = 0; nt < 4; nt++)
                ldm_x4t(bf[nt], bb + ((kb + lr) * BSTR + wn * 64 + nt * 16 + lc) * 2);
#pragma unroll
            for (int mt = 0; mt < 2; mt++)
#pragma unroll
                for (int n8 = 0; n8 < 8; n8++)
                    mma16816(acc[mt][n8], af[mt], &bf[n8 >> 1][(n8 & 1) * 2]);

            // pass 2: Ahi x Wlo
#pragma unroll
            for (int nt = 0; nt < 4; nt++)
                ldm_x4t(bf[nt], bb + ((32 + kb + lr) * BSTR + wn * 64 + nt * 16 + lc) * 2);
#pragma unroll
            for (int mt = 0; mt < 2; mt++)
#pragma unroll
                for (int n8 = 0; n8 < 8; n8++)
                    mma16816(acc[mt][n8], af[mt], &bf[n8 >> 1][(n8 & 1) * 2]);

            // pass 3: Alo x Whi
#pragma unroll
            for (int mt = 0; mt < 2; mt++)
                ldm_x4(af[mt], alob + ((wm * 32 + mt * 16 + lr) * ASTR + kb + lc) * 2);
#pragma unroll
            for (int nt = 0; nt < 4; nt++)
                ldm_x4t(bf[nt], bb + ((kb + lr) * BSTR + wn * 64 + nt * 16 + lc) * 2);
#pragma unroll
            for (int mt = 0; mt < 2; mt++)
#pragma unroll
                for (int n8 = 0; n8 < 8; n8++)
                    mma16816(acc[mt][n8], af[mt], &bf[n8 >> 1][(n8 & 1) * 2]);
        }

        if (more) {
            stx(nxt);
            asm volatile("cp.async.wait_group 0;\n");
        }
        __syncthreads();
    }

    // Epilogue: write g_h
    int r = lane >> 2, cq = lane & 3;
#pragma unroll
    for (int mt = 0; mt < 2; mt++) {
        int row0 = rowBase + wm * 32 + mt * 16 + r;
        int row1 = row0 + 8;
#pragma unroll
        for (int n8 = 0; n8 < 8; n8++) {
            int col = wn * 64 + n8 * 8 + cq * 2;
            if (row0 < NN)
                *reinterpret_cast<float2*>(&g_h[(size_t)row0 * HC + col]) =
                    make_float2(acc[mt][n8][0], acc[mt][n8][1]);
            if (row1 < NN)
                *reinterpret_cast<float2*>(&g_h[(size_t)row1 * HC + col]) =
                    make_float2(acc[mt][n8][2], acc[mt][n8][3]);
        }
    }
}

// ---------------------------------------------------------------------------
// Aggregate: warp per destination node. Self-loop + CSR gather (norm inline)
// + bias + PReLU.
// ---------------------------------------------------------------------------
__global__ __launch_bounds__(256)
void k_agg(float* __restrict__ out, const float* __restrict__ b,
           const float* __restrict__ alpha) {
    int node = blockIdx.x * (blockDim.x >> 5) + (threadIdx.x >> 5);
    int lane = threadIdx.x & 31;
    if (node >= NN) return;

    int s = g_off[node];
    int e = g_off[node + 1];

    float dc = g_dis[node];
    float s2 = dc * dc;
    float4 own = *reinterpret_cast<const float4*>(&g_h[(size_t)node * HC + lane * 4]);
    float4 bb  = *reinterpret_cast<const float4*>(&b[lane * 4]);
    float4 acc = make_float4(fmaf(own.x, s2, bb.x), fmaf(own.y, s2, bb.y),
                             fmaf(own.z, s2, bb.z), fmaf(own.w, s2, bb.w));

    int j = s;
    for (; j + 1 < e; j += 2) {
        int2 e0 = g_csr[j];
        int2 e1 = g_csr[j + 1];
        int r0 = e0.x & 0xFFFF, r1 = e1.x & 0xFFFF;
        float n0 = g_dis[r0] * __int_as_float(e0.y) * dc;
        float n1 = g_dis[r1] * __int_as_float(e1.y) * dc;
        float4 v0 = *reinterpret_cast<const float4*>(&g_h[(size_t)r0 * HC + lane * 4]);
        float4 v1 = *reinterpret_cast<const float4*>(&g_h[(size_t)r1 * HC + lane * 4]);
        acc.x = fmaf(v0.x, n0, acc.x); acc.y = fmaf(v0.y, n0, acc.y);
        acc.z = fmaf(v0.z, n0, acc.z); acc.w = fmaf(v0.w, n0, acc.w);
        acc.x = fmaf(v1.x, n1, acc.x); acc.y = fmaf(v1.y, n1, acc.y);
        acc.z = fmaf(v1.z, n1, acc.z); acc.w = fmaf(v1.w, n1, acc.w);
    }
    if (j < e) {
        int2 e0 = g_csr[j];
        int r0 = e0.x & 0xFFFF;
        float n0 = g_dis[r0] * __int_as_float(e0.y) * dc;
        float4 v0 = *reinterpret_cast<const float4*>(&g_h[(size_t)r0 * HC + lane * 4]);
        acc.x = fmaf(v0.x, n0, acc.x); acc.y = fmaf(v0.y, n0, acc.y);
        acc.z = fmaf(v0.z, n0, acc.z); acc.w = fmaf(v0.w, n0, acc.w);
    }

    float4 aa = *reinterpret_cast<const float4*>(&alpha[lane * 4]);
    acc.x = acc.x >= 0.f ? acc.x : aa.x * acc.x;
    acc.y = acc.y >= 0.f ? acc.y : aa.y * acc.y;
    acc.z = acc.z >= 0.f ? acc.z : aa.z * acc.z;
    acc.w = acc.w >= 0.f ? acc.w : aa.w * acc.w;
    *reinterpret_cast<float4*>(&out[(size_t)node * HC + lane * 4]) = acc;
}

// ---------------------------------------------------------------------------
extern "C" void kernel_launch(void* const* d_in, const int* in_sizes, int n_in,
                              void* d_out, int out_size) {
    const float* x  = (const float*)d_in[0];
    const int*   ei = (const int*)d_in[1];     // int32 (JAX x64-disabled downcast)
    const float* ew = (const float*)d_in[2];
    const float* W  = (const float*)d_in[3];
    const float* b  = (const float*)d_in[4];
    const float* al = (const float*)d_in[5];
    float* out = (float*)d_out;

    static bool smem_set = false;
    if (!smem_set) {
        cudaFuncSetAttribute(k_gemm_mma,
                             cudaFuncAttributeMaxDynamicSharedMemorySize, SMEM_BYTES);
        smem_set = true;
    }

    k_prep<<<256, 256>>>(W);                       // zero cnt + barrier + wcat
    k_build<<<BB, BT>>>(ei, ew);                   // fused count/scan/fill/degdis
    k_gemm_mma<<<NROWS_PAD / GM, 256, SMEM_BYTES>>>(x);
    k_agg<<<(NN * 32 + 255) / 256, 256>>>(out, b, al);
}

// round 17
// speedup vs baseline: 1.5768x; 1.5768x over previous
#include <cuda_runtime.h>
#include <cuda_bf16.h>
#include <cstdint>

#define NN 50000
#define NE 800000
#define INC 256
#define HC  128

#define NROWS_PAD 50048   // 391 * 128

// Scratch (no cudaMalloc allowed)
__device__ float g_h[(size_t)NN * HC];
__device__ float g_deg[NN];
__device__ float g_dis[NN];
__device__ int   g_cnt[NN];
__device__ int   g_off[NN + 1];
__device__ int   g_cursor[NN];
__device__ int2  g_csr[NE];                   // {row | col<<16, ew_bits}
__device__ __nv_bfloat16 g_wcat[512 * 128];   // [Whi(256); Wlo(256)]

// Fused-scan config: 49 blocks x 1024 threads (co-resident -> grid barrier OK)
#define SB 49
#define ST 1024
__device__ int g_bsum[SB];
__device__ unsigned g_barcnt;
__device__ volatile unsigned g_barsense;

// ---------------------------------------------------------------------------
// Prep: zero cnt/deg, reset barrier, build wcat = [Whi(256); Wlo(256)] bf16
// ---------------------------------------------------------------------------
__global__ void k_prep(const float* __restrict__ W) {
    int i = blockIdx.x * blockDim.x + threadIdx.x;   // 65536 threads
    if (i == 0) { g_barcnt = 0; g_barsense = 0; }
    if (i < NN) { g_cnt[i] = 0; g_deg[i] = 1.0f; }   // self-loop weight
    if (i < 512 * 128) {
        int kr = i >> 7, c = i & 127;
        float w = W[(size_t)(kr & 255) * 128 + c];
        __nv_bfloat16 h = __float2bfloat16(w);
        g_wcat[i] = (kr >= 256) ? __float2bfloat16(w - __bfloat162float(h)) : h;
    }
}

// ---------------------------------------------------------------------------
// GEMM helpers (bf16 split mma)
// ---------------------------------------------------------------------------
#define GM 128
#define GK 32
#define NCH (INC / GK)      // 8 chunks
#define ASTR 40             // bf16 units (80B row stride: ldmatrix conflict-free)
#define BSTR 136            // (272B row stride)
#define NGB (NROWS_PAD / GM)              // 391 gemm blocks
#define NCB ((NE + 255) / 256)            // 3125 count blocks

#define AHI_OFF 0
#define ALO_OFF (2 * GM * ASTR)
#define B_OFF   (4 * GM * ASTR)
#define SMEM_ELEMS (4 * GM * ASTR + 2 * 64 * BSTR)
#define SMEM_BYTES (SMEM_ELEMS * 2)

__device__ __forceinline__ void cp16(void* s, const void* g) {
    uint32_t sa = (uint32_t)__cvta_generic_to_shared(s);
    asm volatile("cp.async.cg.shared.global [%0], [%1], 16;\n" :: "r"(sa), "l"(g));
}
__device__ __forceinline__ void ldm_x4(uint32_t* r, uint32_t a) {
    asm volatile("ldmatrix.sync.aligned.m8n8.x4.shared.b16 {%0,%1,%2,%3}, [%4];"
                 : "=r"(r[0]), "=r"(r[1]), "=r"(r[2]), "=r"(r[3]) : "r"(a));
}
__device__ __forceinline__ void ldm_x4t(uint32_t* r, uint32_t a) {
    asm volatile("ldmatrix.sync.aligned.m8n8.x4.trans.shared.b16 {%0,%1,%2,%3}, [%4];"
                 : "=r"(r[0]), "=r"(r[1]), "=r"(r[2]), "=r"(r[3]) : "r"(a));
}
__device__ __forceinline__ void mma16816(float* c, const uint32_t* a, const uint32_t* b) {
    asm volatile("mma.sync.aligned.m16n8k16.row.col.f32.bf16.bf16.f32 "
                 "{%0,%1,%2,%3}, {%4,%5,%6,%7}, {%8,%9}, {%0,%1,%2,%3};"
                 : "+f"(c[0]), "+f"(c[1]), "+f"(c[2]), "+f"(c[3])
                 : "r"(a[0]), "r"(a[1]), "r"(a[2]), "r"(a[3]), "r"(b[0]), "r"(b[1]));
}

__device__ __forceinline__ uint2 pack_hi(float4 v) {
    __nv_bfloat16 h0 = __float2bfloat16(v.x), h1 = __float2bfloat16(v.y);
    __nv_bfloat16 h2 = __float2bfloat16(v.z), h3 = __float2bfloat16(v.w);
    uint2 p;
    p.x = ((uint32_t)__bfloat16_as_ushort(h1) << 16) | __bfloat16_as_ushort(h0);
    p.y = ((uint32_t)__bfloat16_as_ushort(h3) << 16) | __bfloat16_as_ushort(h2);
    return p;
}
__device__ __forceinline__ uint2 pack_lo(float4 v) {
    __nv_bfloat16 h0 = __float2bfloat16(v.x), h1 = __float2bfloat16(v.y);
    __nv_bfloat16 h2 = __float2bfloat16(v.z), h3 = __float2bfloat16(v.w);
    __nv_bfloat16 l0 = __float2bfloat16(v.x - __bfloat162float(h0));
    __nv_bfloat16 l1 = __float2bfloat16(v.y - __bfloat162float(h1));
    __nv_bfloat16 l2 = __float2bfloat16(v.z - __bfloat162float(h2));
    __nv_bfloat16 l3 = __float2bfloat16(v.w - __bfloat162float(h3));
    uint2 p;
    p.x = ((uint32_t)__bfloat16_as_ushort(l1) << 16) | __bfloat16_as_ushort(l0);
    p.y = ((uint32_t)__bfloat16_as_ushort(l3) << 16) | __bfloat16_as_ushort(l2);
    return p;
}

// ---------------------------------------------------------------------------
// Hybrid: blocks [0,NGB) run the split GEMM; blocks [NGB, NGB+NCB) run the
// edge histogram + degree accumulation (independent work, fills gemm's ragged
// second wave).
// ---------------------------------------------------------------------------
__global__ __launch_bounds__(256, 2)
void k_gemm_count(const float* __restrict__ x, const int* __restrict__ ei,
                  const float* __restrict__ ew) {
    if (blockIdx.x >= NGB) {
        int e = (blockIdx.x - NGB) * 256 + threadIdx.x;
        if (e < NE) {
            int c = ei[NE + e];
            atomicAdd(&g_cnt[c], 1);
            atomicAdd(&g_deg[c], ew[e]);
        }
        return;
    }

    extern __shared__ __nv_bfloat16 smem[];
    __nv_bfloat16* Ahi = smem + AHI_OFF;
    __nv_bfloat16* Alo = smem + ALO_OFF;
    __nv_bfloat16* Bs  = smem + B_OFF;

    int tid = threadIdx.x;
    int wid = tid >> 5, lane = tid & 31;
    int wm = wid >> 1, wn = wid & 1;       // 4x2 warps: 32 rows x 64 cols
    int rowBase = blockIdx.x * GM;

    float acc[2][8][4];
#pragma unroll
    for (int i = 0; i < 2; i++)
#pragma unroll
        for (int j = 0; j < 8; j++)
#pragma unroll
            for (int q = 0; q < 4; q++) acc[i][j][q] = 0.0f;

    float4 xstage[4];

    auto ldx = [&](int c) {
        int xcol = c * GK;
#pragma unroll
        for (int l = 0; l < 4; l++) {
            int idx = tid + l * 256;
            int r  = idx >> 3;
            int c8 = idx & 7;
            int gr = rowBase + r;
            float4 v = make_float4(0.f, 0.f, 0.f, 0.f);
            if (gr < NN)
                v = *reinterpret_cast<const float4*>(&x[(size_t)gr * INC + xcol + c8 * 4]);
            xstage[l] = v;
        }
    };
    auto stx = [&](int buf) {
#pragma unroll
        for (int l = 0; l < 4; l++) {
            int idx = tid + l * 256;
            int r  = idx >> 3;
            int c8 = idx & 7;
            *reinterpret_cast<uint2*>(&Ahi[buf * GM * ASTR + r * ASTR + c8 * 4]) =
                pack_hi(xstage[l]);
            *reinterpret_cast<uint2*>(&Alo[buf * GM * ASTR + r * ASTR + c8 * 4]) =
                pack_lo(xstage[l]);
        }
    };
    auto ldb = [&](int c, int buf) {
        int kk = c * GK;
#pragma unroll
        for (int l = 0; l < 4; l++) {
            int idx = tid + l * 256;
            int kr = idx >> 4;            // 64 rows (0..31 hi, 32..63 lo)
            int cq = idx & 15;
            int srow = (kr < 32) ? (kk + kr) : (256 + kk + (kr - 32));
            cp16(&Bs[buf * 64 * BSTR + kr * BSTR + cq * 8],
                 &g_wcat[(size_t)srow * 128 + cq * 8]);
        }
        asm volatile("cp.async.commit_group;\n");
    };

    ldx(0); ldb(0, 0); stx(0);
    asm volatile("cp.async.wait_group 0;\n");
    __syncthreads();

    for (int c = 0; c < NCH; c++) {
        int cur = c & 1, nxt = cur ^ 1;
        bool more = (c + 1 < NCH);
        if (more) { ldx(c + 1); ldb(c + 1, nxt); }

        uint32_t ahib = (uint32_t)__cvta_generic_to_shared(&Ahi[cur * GM * ASTR]);
        uint32_t alob = (uint32_t)__cvta_generic_to_shared(&Alo[cur * GM * ASTR]);
        uint32_t bb   = (uint32_t)__cvta_generic_to_shared(&Bs[cur * 64 * BSTR]);
        int lr = lane & 15, lc = (lane >> 4) * 8;

#pragma unroll
        for (int ks = 0; ks < 2; ks++) {
            int kb = ks * 16;
            uint32_t af[2][4], bf[4][4];

            // pass 1: Ahi x Whi
#pragma unroll
            for (int mt = 0; mt < 2; mt++)
                ldm_x4(af[mt], ahib + ((wm * 32 + mt * 16 + lr) * ASTR + kb + lc) * 2);
#pragma unroll
            for (int nt = 0; nt < 4; nt++)
                ldm_x4t(bf[nt], bb + ((kb + lr) * BSTR + wn * 64 + nt * 16 + lc) * 2);
#pragma unroll
            for (int mt = 0; mt < 2; mt++)
#pragma unroll
                for (int n8 = 0; n8 < 8; n8++)
                    mma16816(acc[mt][n8], af[mt], &bf[n8 >> 1][(n8 & 1) * 2]);

            // pass 2: Ahi x Wlo
#pragma unroll
            for (int nt = 0; nt < 4; nt++)
                ldm_x4t(bf[nt], bb + ((32 + kb + lr) * BSTR + wn * 64 + nt * 16 + lc) * 2);
#pragma unroll
            for (int mt = 0; mt < 2; mt++)
#pragma unroll
                for (int n8 = 0; n8 < 8; n8++)
                    mma16816(acc[mt][n8], af[mt], &bf[n8 >> 1][(n8 & 1) * 2]);

            // pass 3: Alo x Whi
#pragma unroll
            for (int mt = 0; mt < 2; mt++)
                ldm_x4(af[mt], alob + ((wm * 32 + mt * 16 + lr) * ASTR + kb + lc) * 2);
#pragma unroll
            for (int nt = 0; nt < 4; nt++)
                ldm_x4t(bf[nt], bb + ((kb + lr) * BSTR + wn * 64 + nt * 16 + lc) * 2);
#pragma unroll
            for (int mt = 0; mt < 2; mt++)
#pragma unroll
                for (int n8 = 0; n8 < 8; n8++)
                    mma16816(acc[mt][n8], af[mt], &bf[n8 >> 1][(n8 & 1) * 2]);
        }

        if (more) {
            stx(nxt);
            asm volatile("cp.async.wait_group 0;\n");
        }
        __syncthreads();
    }

    int r = lane >> 2, cq = lane & 3;
#pragma unroll
    for (int mt = 0; mt < 2; mt++) {
        int row0 = rowBase + wm * 32 + mt * 16 + r;
        int row1 = row0 + 8;
#pragma unroll
        for (int n8 = 0; n8 < 8; n8++) {
            int col = wn * 64 + n8 * 8 + cq * 2;
            if (row0 < NN)
                *reinterpret_cast<float2*>(&g_h[(size_t)row0 * HC + col]) =
                    make_float2(acc[mt][n8][0], acc[mt][n8][1]);
            if (row1 < NN)
                *reinterpret_cast<float2*>(&g_h[(size_t)row1 * HC + col]) =
                    make_float2(acc[mt][n8][2], acc[mt][n8][3]);
        }
    }
}

// ---------------------------------------------------------------------------
// Fused scan (49 blocks x 1024, one grid barrier): exclusive prefix of g_cnt
// -> g_off/g_cursor; also dis = rsqrt(deg) elementwise.
// ---------------------------------------------------------------------------
__global__ __launch_bounds__(ST, 1)
void k_scan() {
    __shared__ int warpsum[32];
    __shared__ int s_pref;
    int tid = threadIdx.x, lane = tid & 31, wid = tid >> 5;
    int bid = blockIdx.x;
    int i = bid * ST + tid;

    if (i < NN) g_dis[i] = rsqrtf(g_deg[i]);   // deg >= 1 always

    int v = (i < NN) ? g_cnt[i] : 0;
    int x = v;
#pragma unroll
    for (int o = 1; o < 32; o <<= 1) {
        int t = __shfl_up_sync(0xFFFFFFFFu, x, o);
        if (lane >= o) x += t;
    }
    if (lane == 31) warpsum[wid] = x;
    __syncthreads();
    if (wid == 0) {
        int w = warpsum[lane];
#pragma unroll
        for (int o = 1; o < 32; o <<= 1) {
            int t = __shfl_up_sync(0xFFFFFFFFu, w, o);
            if (lane >= o) w += t;
        }
        warpsum[lane] = w;
    }
    __syncthreads();
    int pre = (wid > 0) ? warpsum[wid - 1] : 0;
    int excl = pre + x - v;                    // block-local exclusive
    int btot = warpsum[31];
    if (tid == 0) g_bsum[bid] = btot;

    // grid barrier (49 co-resident blocks)
    __syncthreads();
    if (tid == 0) {
        __threadfence();
        unsigned arr = atomicAdd(&g_barcnt, 1);
        if (arr == SB - 1) {
            g_barcnt = 0;
            __threadfence();
            g_barsense = 1;
        } else {
            while (g_barsense != 1) __nanosleep(64);
        }
        __threadfence();
    }
    __syncthreads();

    // prefix of block sums (warp 0)
    if (wid == 0) {
        int a = (lane < bid) ? g_bsum[lane] : 0;
        int b2 = (lane + 32 < bid) ? g_bsum[lane + 32] : 0;
        int s = a + b2;
#pragma unroll
        for (int o = 16; o > 0; o >>= 1)
            s += __shfl_xor_sync(0xFFFFFFFFu, s, o);
        if (lane == 0) s_pref = s;
    }
    __syncthreads();

    if (i < NN) {
        int o = s_pref + excl;
        g_off[i] = o;
        g_cursor[i] = o;
    }
    if (bid == SB - 1 && tid == ST - 1)
        g_off[NN] = s_pref + excl + v;
}

// ---------------------------------------------------------------------------
// Fill CSR buckets: packed {row | col<<16, ew}
// ---------------------------------------------------------------------------
__global__ void k_fill(const int* __restrict__ ei,
                       const float* __restrict__ ew) {
    int e = blockIdx.x * blockDim.x + threadIdx.x;
    if (e < NE) {
        int r = ei[e];
        int c = ei[NE + e];
        int pos = atomicAdd(&g_cursor[c], 1);
        g_csr[pos] = make_int2(r | (c << 16), __float_as_int(ew[e]));
    }
}

// ---------------------------------------------------------------------------
// Aggregate: warp per destination node, 4-edge unroll for MLP.
// Self-loop + CSR gather (norm inline) + bias + PReLU.
// ---------------------------------------------------------------------------
__global__ __launch_bounds__(256)
void k_agg(float* __restrict__ out, const float* __restrict__ b,
           const float* __restrict__ alpha) {
    int node = blockIdx.x * (blockDim.x >> 5) + (threadIdx.x >> 5);
    int lane = threadIdx.x & 31;
    if (node >= NN) return;

    int s = g_off[node];
    int e = g_off[node + 1];

    float dc = g_dis[node];
    float s2 = dc * dc;
    float4 own = *reinterpret_cast<const float4*>(&g_h[(size_t)node * HC + lane * 4]);
    float4 bb  = *reinterpret_cast<const float4*>(&b[lane * 4]);
    float4 acc = make_float4(fmaf(own.x, s2, bb.x), fmaf(own.y, s2, bb.y),
                             fmaf(own.z, s2, bb.z), fmaf(own.w, s2, bb.w));

    int j = s;
    for (; j + 3 < e; j += 4) {
        int2 e0 = g_csr[j], e1 = g_csr[j + 1], e2 = g_csr[j + 2], e3 = g_csr[j + 3];
        int r0 = e0.x & 0xFFFF, r1 = e1.x & 0xFFFF;
        int r2 = e2.x & 0xFFFF, r3 = e3.x & 0xFFFF;
        float n0 = g_dis[r0] * __int_as_float(e0.y) * dc;
        float n1 = g_dis[r1] * __int_as_float(e1.y) * dc;
        float n2 = g_dis[r2] * __int_as_float(e2.y) * dc;
        float n3 = g_dis[r3] * __int_as_float(e3.y) * dc;
        float4 v0 = *reinterpret_cast<const float4*>(&g_h[(size_t)r0 * HC + lane * 4]);
        float4 v1 = *reinterpret_cast<const float4*>(&g_h[(size_t)r1 * HC + lane * 4]);
        float4 v2 = *reinterpret_cast<const float4*>(&g_h[(size_t)r2 * HC + lane * 4]);
        float4 v3 = *reinterpret_cast<const float4*>(&g_h[(size_t)r3 * HC + lane * 4]);
        acc.x = fmaf(v0.x, n0, acc.x); acc.y = fmaf(v0.y, n0, acc.y);
        acc.z = fmaf(v0.z, n0, acc.z); acc.w = fmaf(v0.w, n0, acc.w);
        acc.x = fmaf(v1.x, n1, acc.x); acc.y = fmaf(v1.y, n1, acc.y);
        acc.z = fmaf(v1.z, n1, acc.z); acc.w = fmaf(v1.w, n1, acc.w);
        acc.x = fmaf(v2.x, n2, acc.x); acc.y = fmaf(v2.y, n2, acc.y);
        acc.z = fmaf(v2.z, n2, acc.z); acc.w = fmaf(v2.w, n2, acc.w);
        acc.x = fmaf(v3.x, n3, acc.x); acc.y = fmaf(v3.y, n3, acc.y);
        acc.z = fmaf(v3.z, n3, acc.z); acc.w = fmaf(v3.w, n3, acc.w);
    }
    for (; j < e; j++) {
        int2 e0 = g_csr[j];
        int r0 = e0.x & 0xFFFF;
        float n0 = g_dis[r0] * __int_as_float(e0.y) * dc;
        float4 v0 = *reinterpret_cast<const float4*>(&g_h[(size_t)r0 * HC + lane * 4]);
        acc.x = fmaf(v0.x, n0, acc.x); acc.y = fmaf(v0.y, n0, acc.y);
        acc.z = fmaf(v0.z, n0, acc.z); acc.w = fmaf(v0.w, n0, acc.w);
    }

    float4 aa = *reinterpret_cast<const float4*>(&alpha[lane * 4]);
    acc.x = acc.x >= 0.f ? acc.x : aa.x * acc.x;
    acc.y = acc.y >= 0.f ? acc.y : aa.y * acc.y;
    acc.z = acc.z >= 0.f ? acc.z : aa.z * acc.z;
    acc.w = acc.w >= 0.f ? acc.w : aa.w * acc.w;
    *reinterpret_cast<float4*>(&out[(size_t)node * HC + lane * 4]) = acc;
}

// ---------------------------------------------------------------------------
extern "C" void kernel_launch(void* const* d_in, const int* in_sizes, int n_in,
                              void* d_out, int out_size) {
    const float* x  = (const float*)d_in[0];
    const int*   ei = (const int*)d_in[1];     // int32 (JAX x64-disabled downcast)
    const float* ew = (const float*)d_in[2];
    const float* W  = (const float*)d_in[3];
    const float* b  = (const float*)d_in[4];
    const float* al = (const float*)d_in[5];
    float* out = (float*)d_out;

    static bool smem_set = false;
    if (!smem_set) {
        cudaFuncSetAttribute(k_gemm_count,
                             cudaFuncAttributeMaxDynamicSharedMemorySize, SMEM_BYTES);
        smem_set = true;
    }

    k_prep<<<256, 256>>>(W);
    k_gemm_count<<<NGB + NCB, 256, SMEM_BYTES>>>(x, ei, ew);
    k_scan<<<SB, ST>>>();
    k_fill<<<NCB, 256>>>(ei, ew);
    k_agg<<<(NN * 32 + 255) / 256, 256>>>(out, b, al);
}